// round 8
// baseline (speedup 1.0000x reference)
#include <cuda_runtime.h>
#include <cuda_fp16.h>
#include <cstdint>

// ---------------------------------------------------------------------------
// DeformableBlock R8: fp16 tensor pipeline, 64x256 GEMM tiles, 2 CTAs/SM.
//   k_prep: x -> NHWC fp16 (flat + 66x66 zero-padded) + both weight preps.
//   k_offconv16: fixed-tap im2col conv via m16n8k16 (offsets, 256->18).
//   k_precomp: bilinear corner idx/weights.
//   k_gemm_fused: on-the-fly bilinear gather + fp16 GEMM + GN partials.
//   k_stats_combine + k_gn_finalize.
// ---------------------------------------------------------------------------

#define BATCH 4
#define CIN   256
#define COUT  256
#define HH    64
#define WW    64
#define HWSZ  4096
#define NPIX  16384
#define KT    9
#define KDIM  2304
#define OCOFF 18
#define GROUPS 32
#define CPG   8
#define NKB   72            // K chunks of 32
#define PD    66            // padded spatial dim
#define PHW   (PD*PD)       // 4356
#define NMB   256           // GEMM M-blocks (64 rows each)

__device__ __align__(16) __half g_xh [NPIX * CIN];          // x NHWC fp16
__device__ __align__(16) __half g_xp [BATCH * PHW * CIN];   // padded NHWC fp16
__device__ __align__(16) __half g_wtB[NKB * 256 * 32];      // deform W tiles
__device__ __align__(16) __half g_wtO[NKB * 32 * 32];       // offset W tiles
__device__ float  g_off [NPIX * OCOFF];                     // offsets (no bias)
__device__ int4   g_sidx[NPIX * KT];
__device__ float4 g_sw  [NPIX * KT];
__device__ float  g_P   [NPIX * COUT];
__device__ float2 g_gnp [NMB * GROUPS];
__device__ float  g_stat[BATCH * GROUPS * 2];

static __device__ __forceinline__ uint32_t sptr(const void* p) {
    return (uint32_t)__cvta_generic_to_shared(p);
}
#define CP_ASYNC16(dst, src) \
    asm volatile("cp.async.cg.shared.global [%0], [%1], 16;\n" :: "r"(dst), "l"(src))
#define CP_COMMIT() asm volatile("cp.async.commit_group;\n")

#define LDMX4(r0, r1, r2, r3, addr)                                         \
    asm volatile("ldmatrix.sync.aligned.m8n8.x4.shared.b16 {%0,%1,%2,%3}, [%4];" \
                 : "=r"(r0), "=r"(r1), "=r"(r2), "=r"(r3) : "r"(addr))

#define MMA16816(d, a, b0, b1)                                              \
    asm volatile(                                                           \
        "mma.sync.aligned.m16n8k16.row.col.f32.f16.f16.f32 "                \
        "{%0,%1,%2,%3}, {%4,%5,%6,%7}, {%8,%9}, {%0,%1,%2,%3};\n"           \
        : "+f"((d)[0]), "+f"((d)[1]), "+f"((d)[2]), "+f"((d)[3])            \
        : "r"((a)[0]), "r"((a)[1]), "r"((a)[2]), "r"((a)[3]),               \
          "r"(b0), "r"(b1))

// ---------------------------------------------------------------------------
// K0: unified prep.  grid (128, 10, 4), 256 threads.
// ---------------------------------------------------------------------------
__global__ __launch_bounds__(256) void k_prep(const float* __restrict__ x,
                                              const float* __restrict__ dw,
                                              const float* __restrict__ ow) {
    __shared__ float tile[32][33];
    int role = blockIdx.y;
    int b = blockIdx.z;
    int t = threadIdx.x;

    if (role < 8) {
        int hw0 = blockIdx.x * 32, c0 = role * 32;
        int tx = t & 31, ty = t >> 5;
#pragma unroll
        for (int i = 0; i < 4; i++) {
            int c = c0 + ty + i * 8;
            tile[ty + i * 8][tx] = x[((long)b * CIN + c) * HWSZ + hw0 + tx];
        }
        __syncthreads();
#pragma unroll
        for (int i = 0; i < 4; i++) {
            int hw = hw0 + ty + i * 8;
            __half v = __float2half_rn(tile[tx][ty + i * 8]);
            g_xh[((size_t)b * HWSZ + hw) * CIN + c0 + tx] = v;
            int h = hw >> 6, w = hw & 63;
            g_xp[((size_t)b * PHW + (h + 1) * PD + (w + 1)) * CIN + c0 + tx] = v;
        }
    } else if (role == 8) {
        uint32_t* xp32 = (uint32_t*)g_xp;
        for (int i = blockIdx.x * 256 + t; i < 260 * 128; i += 128 * 256) {
            int p = i >> 7, word = i & 127;
            int y, xx;
            if (p < 66)       { y = 0;        xx = p; }
            else if (p < 132) { y = 65;       xx = p - 66; }
            else if (p < 196) { y = p - 131;  xx = 0; }
            else              { y = p - 195;  xx = 65; }
            xp32[((size_t)b * PHW + y * PD + xx) * 128 + word] = 0u;
        }
    } else {
        if (b == 0) {
            for (int i = blockIdx.x * 256 + t; i < NKB * 8192; i += 128 * 256) {
                int kb = i >> 13, rem = i & 8191;
                int o = rem >> 5, ko = rem & 31;
                int tap = kb >> 3, c = (kb & 7) * 32 + ko;
                g_wtB[i] = __float2half_rn(dw[(o * CIN + c) * KT + tap]);
            }
        } else if (b == 1) {
            for (int i = blockIdx.x * 256 + t; i < NKB * 1024; i += 128 * 256) {
                int kb = i >> 10, rem = i & 1023;
                int oc = rem >> 5, ko = rem & 31;
                int tap = kb >> 3, c = (kb & 7) * 32 + ko;
                g_wtO[i] = (oc < OCOFF)
                    ? __float2half_rn(ow[(oc * CIN + c) * KT + tap])
                    : __half(0.f);
            }
        }
    }
}

// ---------------------------------------------------------------------------
// K1: offset conv via fp16 MMA.  grid=128, 256 thr.
// ---------------------------------------------------------------------------
__global__ __launch_bounds__(256) void k_offconv16() {
    __shared__ __align__(16) __half sA[3][128 * 40];
    __shared__ __align__(16) __half sB[3][32 * 40];
    uint32_t sbA = sptr(sA), sbB = sptr(sB);

    int t = threadIdx.x, lane = t & 31, wid = t >> 5;
    int m0 = blockIdx.x * 128;
    int r = t >> 1, seg = (t & 1) * 16;
    int pix = m0 + r;
    int b = pix >> 12, h = (pix >> 6) & 63, w = pix & 63;
    size_t basep = (size_t)b * PHW + h * PD + w;
    int brow = t >> 2, bcol = (t & 3) * 8;

    float acc[4][4];
#pragma unroll
    for (int i = 0; i < 4; i++)
#pragma unroll
        for (int q = 0; q < 4; q++) acc[i][q] = 0.f;

#define OLOAD(stg, kb)                                                        \
    do {                                                                      \
        int tap = (kb) >> 3, cb = ((kb) & 7) * 32 + seg;                      \
        const __half* src =                                                   \
            g_xp + (basep + (tap / 3) * PD + (tap % 3)) * CIN + cb;           \
        CP_ASYNC16(sbA + (stg) * 10240 + (r * 40 + seg) * 2, src);            \
        CP_ASYNC16(sbA + (stg) * 10240 + (r * 40 + seg + 8) * 2, src + 8);    \
        if (t < 128)                                                          \
            CP_ASYNC16(sbB + (stg) * 2560 + (brow * 40 + bcol) * 2,           \
                       g_wtO + (kb) * 1024 + brow * 32 + bcol);               \
        CP_COMMIT();                                                          \
    } while (0)

    OLOAD(0, 0);
    OLOAD(1, 1);

    int lrow = lane & 15, lcol = (lane >> 4) * 8;
    for (int c = 0; c < NKB; c++) {
        int st = c % 3;
        if (c + 1 < NKB) {
            asm volatile("cp.async.wait_group 1;" ::: "memory");
        } else {
            asm volatile("cp.async.wait_group 0;" ::: "memory");
        }
        __syncthreads();
#pragma unroll
        for (int ks = 0; ks < 32; ks += 16) {
            int col = ks + lcol;
            uint32_t A0[4], t0, t1, t2, t3;
            LDMX4(A0[0], A0[1], A0[2], A0[3],
                  sbA + st * 10240 + ((wid * 16 + lrow) * 40 + col) * 2);
#pragma unroll
            for (int np = 0; np < 2; np++) {
                LDMX4(t0, t1, t2, t3,
                      sbB + st * 2560 + ((np * 16 + lrow) * 40 + col) * 2);
                MMA16816(acc[np * 2], A0, t0, t2);
                MMA16816(acc[np * 2 + 1], A0, t1, t3);
            }
        }
        if (c + 2 < NKB) OLOAD((c + 2) % 3, c + 2);
    }
#undef OLOAD

    int rb = m0 + wid * 16 + (lane >> 2);
#pragma unroll
    for (int nt = 0; nt < 3; nt++) {
        int col = nt * 8 + (lane & 3) * 2;
        if (col < OCOFF) {
            g_off[rb * OCOFF + col] = acc[nt][0];
            g_off[(rb + 8) * OCOFF + col] = acc[nt][2];
        }
        if (col + 1 < OCOFF) {
            g_off[rb * OCOFF + col + 1] = acc[nt][1];
            g_off[(rb + 8) * OCOFF + col + 1] = acc[nt][3];
        }
    }
}

// ---------------------------------------------------------------------------
// K2: precompute bilinear corner indices + weights (adds bias)
// ---------------------------------------------------------------------------
__global__ void k_precomp(const float* __restrict__ ob) {
    int i = blockIdx.x * 256 + threadIdx.x;
    if (i >= NPIX * KT) return;
    int tp = i % 9, pix = i / 9;
    float dy = ob[2 * tp]     + g_off[pix * OCOFF + 2 * tp];
    float dx = ob[2 * tp + 1] + g_off[pix * OCOFF + 2 * tp + 1];
    int h = (pix >> 6) & 63, w = pix & 63;
    int ky = tp / 3, kx = tp % 3;
    float py = (float)(h - 1 + ky) + dy;
    float px = (float)(w - 1 + kx) + dx;
    float y0f = floorf(py), x0f = floorf(px);
    float ty = py - y0f, tx = px - x0f;
    int y0 = (int)y0f, x0 = (int)x0f;
    int y1 = y0 + 1, x1 = x0 + 1;
    float vy0 = (y0 >= 0 && y0 < HH) ? 1.f : 0.f;
    float vy1 = (y1 >= 0 && y1 < HH) ? 1.f : 0.f;
    float vx0 = (x0 >= 0 && x0 < WW) ? 1.f : 0.f;
    float vx1 = (x1 >= 0 && x1 < WW) ? 1.f : 0.f;
    int yc0 = min(max(y0, 0), HH - 1), yc1 = min(max(y1, 0), HH - 1);
    int xc0 = min(max(x0, 0), WW - 1), xc1 = min(max(x1, 0), WW - 1);
    g_sidx[i] = make_int4(yc0 * WW + xc0, yc0 * WW + xc1,
                          yc1 * WW + xc0, yc1 * WW + xc1);
    g_sw[i] = make_float4((1.f - ty) * (1.f - tx) * vy0 * vx0,
                          (1.f - ty) * tx * vy0 * vx1,
                          ty * (1.f - tx) * vy1 * vx0,
                          ty * tx * vy1 * vx1);
}

// ---------------------------------------------------------------------------
// K3: FUSED gather + fp16 GEMM + GN partials.
//   64x256 tile, 256 thr (8 warps: wm=wid&1 -> 32 rows, wn=wid>>1 -> 64 cols),
//   BK=32, 3-stage, grid=256, 2 CTAs/SM.
// ---------------------------------------------------------------------------
#define ASTRIDE 40
#define A_OFF(s)  ((s) * 5120)              // 64*40*2
#define B_OFF(s)  (15360 + (s) * 20480)     // 256*40*2
#define GEMM_SMEM (15360 + 3 * 20480)       // 76800

__global__ __launch_bounds__(256, 2) void k_gemm_fused() {
    extern __shared__ __align__(16) char smem[];
    uint32_t sb = sptr(smem);

    int m0 = blockIdx.x * 64;
    int b  = blockIdx.x >> 6;
    int t = threadIdx.x, lane = t & 31, wid = t >> 5;
    int wm = wid & 1, wn = wid >> 1;
    int lrow = lane & 15, lcol = (lane >> 4) * 8;

    // gather assignment: 1 row (pixel), 8 channels
    int r  = t >> 2;
    int s8 = (t & 3) * 8;
    int pixg = m0 + r;
    const __half* xb = g_xh + (size_t)b * HWSZ * CIN;

    float acc[2][8][4];
#pragma unroll
    for (int i = 0; i < 2; i++)
#pragma unroll
        for (int j = 0; j < 8; j++)
#pragma unroll
            for (int q = 0; q < 4; q++) acc[i][j][q] = 0.f;

    int4   I;
    float4 Wq;
    uint4  c0v, c1v, c2v, c3v;

#define GATHER_LDG(cn)                                                        \
    do {                                                                      \
        if (((cn) & 7) == 0) {                                                \
            int tap = (cn) >> 3;                                              \
            I  = g_sidx[pixg * 9 + tap];                                      \
            Wq = g_sw[pixg * 9 + tap];                                        \
        }                                                                     \
        const __half* xc = xb + ((cn) & 7) * 32 + s8;                         \
        c0v = *(const uint4*)(xc + (size_t)I.x * CIN);                        \
        c1v = *(const uint4*)(xc + (size_t)I.y * CIN);                        \
        c2v = *(const uint4*)(xc + (size_t)I.z * CIN);                        \
        c3v = *(const uint4*)(xc + (size_t)I.w * CIN);                        \
    } while (0)

#define GATHER_STORE(stg)                                                     \
    do {                                                                      \
        const __half2* h0 = (const __half2*)&c0v;                             \
        const __half2* h1 = (const __half2*)&c1v;                             \
        const __half2* h2 = (const __half2*)&c2v;                             \
        const __half2* h3 = (const __half2*)&c3v;                             \
        __half2 outv[4];                                                      \
        _Pragma("unroll")                                                     \
        for (int j = 0; j < 4; j++) {                                         \
            float2 f0 = __half22float2(h0[j]);                                \
            float2 f1 = __half22float2(h1[j]);                                \
            float2 f2 = __half22float2(h2[j]);                                \
            float2 f3 = __half22float2(h3[j]);                                \
            float2 rr;                                                        \
            rr.x = Wq.x * f0.x + Wq.y * f1.x + Wq.z * f2.x + Wq.w * f3.x;     \
            rr.y = Wq.x * f0.y + Wq.y * f1.y + Wq.z * f2.y + Wq.w * f3.y;     \
            outv[j] = __float22half2_rn(rr);                                  \
        }                                                                     \
        *(uint4*)(smem + A_OFF(stg) + (r * ASTRIDE + s8) * 2) =               \
            *(const uint4*)outv;                                              \
    } while (0)

#define LOAD_B(stg, kb)                                                       \
    do {                                                                      \
        const __half* bs = g_wtB + (kb) * 8192 + t * 32;                      \
        uint32_t bd = sb + B_OFF(stg) + t * ASTRIDE * 2;                      \
        CP_ASYNC16(bd,      bs);                                              \
        CP_ASYNC16(bd + 16, bs + 8);                                          \
        CP_ASYNC16(bd + 32, bs + 16);                                         \
        CP_ASYNC16(bd + 48, bs + 24);                                         \
        CP_COMMIT();                                                          \
    } while (0)

    GATHER_LDG(0);  GATHER_STORE(0);
    GATHER_LDG(1);  GATHER_STORE(1);
    LOAD_B(0, 0);
    LOAD_B(1, 1);

    for (int c = 0; c < NKB; c++) {
        int st = c % 3;
        if (c + 2 < NKB) GATHER_LDG(c + 2);
        if (c + 1 < NKB) {
            asm volatile("cp.async.wait_group 1;" ::: "memory");
        } else {
            asm volatile("cp.async.wait_group 0;" ::: "memory");
        }
        __syncthreads();

        uint32_t Ab = sb + A_OFF(st);
        uint32_t Bb = sb + B_OFF(st);
#pragma unroll
        for (int ks = 0; ks < 32; ks += 16) {
            int col = ks + lcol;
            uint32_t A0[4], A1[4], t0, t1, t2, t3;
            LDMX4(A0[0], A0[1], A0[2], A0[3],
                  Ab + ((wm * 32 + lrow) * ASTRIDE + col) * 2);
            LDMX4(A1[0], A1[1], A1[2], A1[3],
                  Ab + ((wm * 32 + 16 + lrow) * ASTRIDE + col) * 2);
#pragma unroll
            for (int np = 0; np < 4; np++) {
                LDMX4(t0, t1, t2, t3,
                      Bb + ((wn * 64 + np * 16 + lrow) * ASTRIDE + col) * 2);
                MMA16816(acc[0][np * 2], A0, t0, t2);
                MMA16816(acc[1][np * 2], A1, t0, t2);
                MMA16816(acc[0][np * 2 + 1], A0, t1, t3);
                MMA16816(acc[1][np * 2 + 1], A1, t1, t3);
            }
        }

        if (c + 2 < NKB) {
            int wst = (c + 2) % 3;
            GATHER_STORE(wst);
            LOAD_B(wst, c + 2);
        }
    }
#undef GATHER_LDG
#undef GATHER_STORE
#undef LOAD_B

    // ---- write P ----
#pragma unroll
    for (int mt = 0; mt < 2; mt++) {
        int row = m0 + wm * 32 + mt * 16 + (lane >> 2);
#pragma unroll
        for (int nt = 0; nt < 8; nt++) {
            int col = wn * 64 + nt * 8 + (lane & 3) * 2;
            *(float2*)&g_P[(size_t)row * COUT + col] =
                make_float2(acc[mt][nt][0], acc[mt][nt][1]);
            *(float2*)&g_P[(size_t)(row + 8) * COUT + col] =
                make_float2(acc[mt][nt][2], acc[mt][nt][3]);
        }
    }

    // ---- GN partial sums (deterministic) ----
    __syncthreads();
    float* sgn = (float*)smem;              // [32 groups][2 wm][2]
#pragma unroll
    for (int nt = 0; nt < 8; nt++) {
        float s = 0.f, ss = 0.f;
#pragma unroll
        for (int mt = 0; mt < 2; mt++)
#pragma unroll
            for (int q = 0; q < 4; q++) {
                float v = acc[mt][nt][q];
                s += v;  ss += v * v;
            }
#pragma unroll
        for (int off = 16; off >= 1; off >>= 1) {
            s  += __shfl_xor_sync(0xffffffffu, s, off);
            ss += __shfl_xor_sync(0xffffffffu, ss, off);
        }
        if (lane == 0) {
            int g = wn * 8 + nt;
            sgn[(g * 2 + wm) * 2 + 0] = s;
            sgn[(g * 2 + wm) * 2 + 1] = ss;
        }
    }
    __syncthreads();
    if (t < GROUPS) {
        float s  = sgn[(t * 2 + 0) * 2 + 0] + sgn[(t * 2 + 1) * 2 + 0];
        float ss = sgn[(t * 2 + 0) * 2 + 1] + sgn[(t * 2 + 1) * 2 + 1];
        g_gnp[blockIdx.x * GROUPS + t] = make_float2(s, ss);
    }
}

// ---------------------------------------------------------------------------
// K4: combine GN partials -> mean / rstd
// ---------------------------------------------------------------------------
__global__ void k_stats_combine() {
    int t = threadIdx.x;
    int b = t >> 5, g = t & 31;
    float s = 0.f, ss = 0.f;
    for (int blk = 0; blk < 64; blk++) {
        float2 v = g_gnp[(b * 64 + blk) * GROUPS + g];
        s += v.x;  ss += v.y;
    }
    float inv = 1.f / (float)(CPG * HWSZ);
    float mean = s * inv;
    float var  = ss * inv - mean * mean;
    g_stat[t * 2]     = mean;
    g_stat[t * 2 + 1] = rsqrtf(var + 1e-5f);
}

// ---------------------------------------------------------------------------
// K5: normalize + affine + ReLU + NHWC->NCHW into d_out
// ---------------------------------------------------------------------------
__global__ void k_gn_finalize(float* __restrict__ out,
                              const float* __restrict__ gamma,
                              const float* __restrict__ beta) {
    __shared__ float tile[32][33];
    int b = blockIdx.z, hw0 = blockIdx.x * 32, o0 = blockIdx.y * 32;
    int tx = threadIdx.x, ty = threadIdx.y;

    int o = o0 + tx;
    int g = o >> 3;
    float mean = g_stat[(b * GROUPS + g) * 2];
    float rstd = g_stat[(b * GROUPS + g) * 2 + 1];
    float ga = gamma[o], be = beta[o];

#pragma unroll
    for (int i = 0; i < 4; i++) {
        int hw = hw0 + ty + i * 8;
        float v = g_P[(long)(b * HWSZ + hw) * COUT + o];
        v = (v - mean) * rstd * ga + be;
        tile[ty + i * 8][tx] = fmaxf(v, 0.f);
    }
    __syncthreads();
#pragma unroll
    for (int i = 0; i < 4; i++) {
        int oo = o0 + ty + i * 8;
        out[((long)b * COUT + oo) * HWSZ + hw0 + tx] = tile[tx][ty + i * 8];
    }
}

// ---------------------------------------------------------------------------
extern "C" void kernel_launch(void* const* d_in, const int* in_sizes, int n_in,
                              void* d_out, int out_size) {
    const float* x  = (const float*)d_in[0];
    const float* ow = (const float*)d_in[1];
    const float* ob = (const float*)d_in[2];
    const float* dw = (const float*)d_in[3];
    const float* ga = (const float*)d_in[4];
    const float* be = (const float*)d_in[5];
    float* out = (float*)d_out;

    cudaFuncSetAttribute(k_gemm_fused,
                         cudaFuncAttributeMaxDynamicSharedMemorySize, GEMM_SMEM);

    k_prep<<<dim3(128, 10, 4), 256>>>(x, dw, ow);
    k_offconv16<<<128, 256>>>();
    k_precomp<<<(NPIX * KT + 255) / 256, 256>>>(ob);
    k_gemm_fused<<<NMB, 256, GEMM_SMEM>>>();
    k_stats_combine<<<1, 128>>>();
    k_gn_finalize<<<dim3(HWSZ / 32, COUT / 32, BATCH), dim3(32, 8)>>>(out, ga, be);
}

// round 9
// speedup vs baseline: 1.2693x; 1.2693x over previous
#include <cuda_runtime.h>
#include <cuda_fp16.h>
#include <cstdint>

// ---------------------------------------------------------------------------
// DeformableBlock R9: fp16 tensor pipeline, BK=64 2-stage GEMM, fused precomp.
//   k_prep: x -> padded NHWC fp16 (66x66) + weight tiles (BK=64 for deform).
//   k_offconv16: offset conv via m16n8k16 + in-register bilinear precomp.
//   k_gemm_fused: gather-from-padded + fp16 GEMM (128x256, BK=64, 2-stage)
//                 + GN partials.   k_stats_combine + k_gn_finalize.
// ---------------------------------------------------------------------------

#define BATCH 4
#define CIN   256
#define COUT  256
#define HH    64
#define WW    64
#define HWSZ  4096
#define NPIX  16384
#define KT    9
#define KDIM  2304
#define OCOFF 18
#define GROUPS 32
#define CPG   8
#define NKB   72            // 32-wide K blocks (offset conv)
#define NKC   36            // 64-wide K chunks (deform GEMM)
#define PD    66
#define PHW   (PD*PD)

__device__ __align__(16) __half g_xp [BATCH * PHW * CIN];   // padded NHWC fp16
__device__ __align__(16) __half g_wtB[NKC * 256 * 64];      // deform W [kc][o][k64]
__device__ __align__(16) __half g_wtO[NKB * 32 * 32];       // offset W tiles
__device__ int4   g_sidx[NPIX * KT];                        // padded corner idx
__device__ float4 g_sw  [NPIX * KT];
__device__ float  g_P   [NPIX * COUT];
__device__ float2 g_gnp [128 * GROUPS];
__device__ float  g_stat[BATCH * GROUPS * 2];

static __device__ __forceinline__ uint32_t sptr(const void* p) {
    return (uint32_t)__cvta_generic_to_shared(p);
}
#define CP_ASYNC16(dst, src) \
    asm volatile("cp.async.cg.shared.global [%0], [%1], 16;\n" :: "r"(dst), "l"(src))
#define CP_COMMIT() asm volatile("cp.async.commit_group;\n")

#define LDMX4(r0, r1, r2, r3, addr)                                         \
    asm volatile("ldmatrix.sync.aligned.m8n8.x4.shared.b16 {%0,%1,%2,%3}, [%4];" \
                 : "=r"(r0), "=r"(r1), "=r"(r2), "=r"(r3) : "r"(addr))

#define MMA16816(d, a, b0, b1)                                              \
    asm volatile(                                                           \
        "mma.sync.aligned.m16n8k16.row.col.f32.f16.f16.f32 "                \
        "{%0,%1,%2,%3}, {%4,%5,%6,%7}, {%8,%9}, {%0,%1,%2,%3};\n"           \
        : "+f"((d)[0]), "+f"((d)[1]), "+f"((d)[2]), "+f"((d)[3])            \
        : "r"((a)[0]), "r"((a)[1]), "r"((a)[2]), "r"((a)[3]),               \
          "r"(b0), "r"(b1))

// ---------------------------------------------------------------------------
// K0: unified prep.  grid (128, 10, 4), 256 threads.
//   role<8 : NCHW -> padded NHWC fp16 transpose
//   role=8 : zero border ring of g_xp
//   role=9 : z=0 -> g_wtB ; z=1 -> g_wtO
// ---------------------------------------------------------------------------
__global__ __launch_bounds__(256) void k_prep(const float* __restrict__ x,
                                              const float* __restrict__ dw,
                                              const float* __restrict__ ow) {
    __shared__ float tile[32][33];
    int role = blockIdx.y;
    int b = blockIdx.z;
    int t = threadIdx.x;

    if (role < 8) {
        int hw0 = blockIdx.x * 32, c0 = role * 32;
        int tx = t & 31, ty = t >> 5;
#pragma unroll
        for (int i = 0; i < 4; i++) {
            int c = c0 + ty + i * 8;
            tile[ty + i * 8][tx] = x[((long)b * CIN + c) * HWSZ + hw0 + tx];
        }
        __syncthreads();
#pragma unroll
        for (int i = 0; i < 4; i++) {
            int hw = hw0 + ty + i * 8;
            __half v = __float2half_rn(tile[tx][ty + i * 8]);
            int h = hw >> 6, w = hw & 63;
            g_xp[((size_t)b * PHW + (h + 1) * PD + (w + 1)) * CIN + c0 + tx] = v;
        }
    } else if (role == 8) {
        uint32_t* xp32 = (uint32_t*)g_xp;
        for (int i = blockIdx.x * 256 + t; i < 260 * 128; i += 128 * 256) {
            int p = i >> 7, word = i & 127;
            int y, xx;
            if (p < 66)       { y = 0;        xx = p; }
            else if (p < 132) { y = 65;       xx = p - 66; }
            else if (p < 196) { y = p - 131;  xx = 0; }
            else              { y = p - 195;  xx = 65; }
            xp32[((size_t)b * PHW + y * PD + xx) * 128 + word] = 0u;
        }
    } else {
        if (b == 0) {
            for (int i = blockIdx.x * 256 + t; i < NKC * 16384; i += 128 * 256) {
                int kc = i >> 14, rem = i & 16383;
                int o = rem >> 6, ko = rem & 63;
                int tap = kc >> 2, c = (kc & 3) * 64 + ko;
                g_wtB[i] = __float2half_rn(dw[(o * CIN + c) * KT + tap]);
            }
        } else if (b == 1) {
            for (int i = blockIdx.x * 256 + t; i < NKB * 1024; i += 128 * 256) {
                int kb = i >> 10, rem = i & 1023;
                int oc = rem >> 5, ko = rem & 31;
                int tap = kb >> 3, c = (kb & 7) * 32 + ko;
                g_wtO[i] = (oc < OCOFF)
                    ? __float2half_rn(ow[(oc * CIN + c) * KT + tap])
                    : __half(0.f);
            }
        }
    }
}

// ---------------------------------------------------------------------------
// K1: offset conv via fp16 MMA + fused bilinear precomp.  grid=128, 256 thr.
// ---------------------------------------------------------------------------
__global__ __launch_bounds__(256) void k_offconv16(const float* __restrict__ ob) {
    __shared__ __align__(16) __half sA[3][128 * 40];
    __shared__ __align__(16) __half sB[3][32 * 40];
    uint32_t sbA = sptr(sA), sbB = sptr(sB);

    int t = threadIdx.x, lane = t & 31, wid = t >> 5;
    int m0 = blockIdx.x * 128;
    int r = t >> 1, seg = (t & 1) * 16;
    int pix0 = m0 + r;
    int b0 = pix0 >> 12, h0 = (pix0 >> 6) & 63, w0 = pix0 & 63;
    size_t basep = (size_t)b0 * PHW + h0 * PD + w0;
    int brow = t >> 2, bcol = (t & 3) * 8;

    float acc[4][4];
#pragma unroll
    for (int i = 0; i < 4; i++)
#pragma unroll
        for (int q = 0; q < 4; q++) acc[i][q] = 0.f;

#define OLOAD(stg, kb)                                                        \
    do {                                                                      \
        int tap = (kb) >> 3, cb = ((kb) & 7) * 32 + seg;                      \
        const __half* src =                                                   \
            g_xp + (basep + (tap / 3) * PD + (tap % 3)) * CIN + cb;           \
        CP_ASYNC16(sbA + (stg) * 10240 + (r * 40 + seg) * 2, src);            \
        CP_ASYNC16(sbA + (stg) * 10240 + (r * 40 + seg + 8) * 2, src + 8);    \
        if (t < 128)                                                          \
            CP_ASYNC16(sbB + (stg) * 2560 + (brow * 40 + bcol) * 2,           \
                       g_wtO + (kb) * 1024 + brow * 32 + bcol);               \
        CP_COMMIT();                                                          \
    } while (0)

    OLOAD(0, 0);
    OLOAD(1, 1);

    int lrow = lane & 15, lcol = (lane >> 4) * 8;
    for (int c = 0; c < NKB; c++) {
        int st = c % 3;
        if (c + 1 < NKB) {
            asm volatile("cp.async.wait_group 1;" ::: "memory");
        } else {
            asm volatile("cp.async.wait_group 0;" ::: "memory");
        }
        __syncthreads();
#pragma unroll
        for (int ks = 0; ks < 32; ks += 16) {
            int col = ks + lcol;
            uint32_t A0[4], t0, t1, t2, t3;
            LDMX4(A0[0], A0[1], A0[2], A0[3],
                  sbA + st * 10240 + ((wid * 16 + lrow) * 40 + col) * 2);
#pragma unroll
            for (int np = 0; np < 2; np++) {
                LDMX4(t0, t1, t2, t3,
                      sbB + st * 2560 + ((np * 16 + lrow) * 40 + col) * 2);
                MMA16816(acc[np * 2], A0, t0, t2);
                MMA16816(acc[np * 2 + 1], A0, t1, t3);
            }
        }
        if (c + 2 < NKB) OLOAD((c + 2) % 3, c + 2);
    }
#undef OLOAD

    // ---- fused bilinear precomp: this thread owns taps nt*4 + (lane&3) ----
    int rb = m0 + wid * 16 + (lane >> 2);
    int q = lane & 3;
#pragma unroll
    for (int nt = 0; nt < 3; nt++) {
        int tap = nt * 4 + q;
        if (tap < 9) {
            float by = ob[2 * tap], bx = ob[2 * tap + 1];
            int ky = tap / 3, kx = tap % 3;
#pragma unroll
            for (int rr = 0; rr < 2; rr++) {
                int pix = rb + rr * 8;
                float dy = acc[nt][rr * 2 + 0] + by;
                float dx = acc[nt][rr * 2 + 1] + bx;
                int h = (pix >> 6) & 63, w = pix & 63;
                float py = (float)(h - 1 + ky) + dy;
                float px = (float)(w - 1 + kx) + dx;
                float y0f = floorf(py), x0f = floorf(px);
                float ty = py - y0f, txf = px - x0f;
                int y0 = (int)y0f, x0 = (int)x0f;
                int y1 = y0 + 1, x1 = x0 + 1;
                float vy0 = (y0 >= 0 && y0 < HH) ? 1.f : 0.f;
                float vy1 = (y1 >= 0 && y1 < HH) ? 1.f : 0.f;
                float vx0 = (x0 >= 0 && x0 < WW) ? 1.f : 0.f;
                float vx1 = (x1 >= 0 && x1 < WW) ? 1.f : 0.f;
                int yc0 = min(max(y0, 0), HH - 1), yc1 = min(max(y1, 0), HH - 1);
                int xc0 = min(max(x0, 0), WW - 1), xc1 = min(max(x1, 0), WW - 1);
                // padded-layout corner indices
                g_sidx[pix * 9 + tap] = make_int4(
                    (yc0 + 1) * PD + xc0 + 1, (yc0 + 1) * PD + xc1 + 1,
                    (yc1 + 1) * PD + xc0 + 1, (yc1 + 1) * PD + xc1 + 1);
                g_sw[pix * 9 + tap] = make_float4(
                    (1.f - ty) * (1.f - txf) * vy0 * vx0,
                    (1.f - ty) * txf * vy0 * vx1,
                    ty * (1.f - txf) * vy1 * vx0,
                    ty * txf * vy1 * vx1);
            }
        }
    }
}

// ---------------------------------------------------------------------------
// K2: FUSED gather + fp16 GEMM + GN partials.
//   128x256 tile, 512 thr (16 warps 4x4), BK=64, 2-stage, grid=128.
// ---------------------------------------------------------------------------
#define ASTRIDE 72                          // halfs per smem row (64 + 8)
#define A_OFF(s)  ((s) * 18432)             // 128*72*2
#define B_OFF(s)  (36864 + (s) * 36864)     // 256*72*2
#define GEMM_SMEM (36864 + 2 * 36864)       // 110592

__global__ __launch_bounds__(512, 1) void k_gemm_fused() {
    extern __shared__ __align__(16) char smem[];
    uint32_t sb = sptr(smem);

    int m0 = blockIdx.x * 128;
    int b  = blockIdx.x >> 5;
    int t = threadIdx.x, lane = t & 31, wid = t >> 5;
    int wm = wid & 3, wn = wid >> 2;
    int lrow = lane & 15, lcol = (lane >> 4) * 8;

    // gather assignment: 1 row (pixel), 16 of the 64 chunk-channels
    int r   = t >> 2;
    int s16 = (t & 3) * 16;
    int pixg = m0 + r;
    const __half* xb = g_xp + (size_t)b * PHW * CIN;

    float acc[2][8][4];
#pragma unroll
    for (int i = 0; i < 2; i++)
#pragma unroll
        for (int j = 0; j < 8; j++)
#pragma unroll
            for (int q = 0; q < 4; q++) acc[i][j][q] = 0.f;

    int4   I;
    float4 Wq;
    uint4  c0v, c1v, c2v, c3v;

#define GATHER_LDG(cn, half)                                                  \
    do {                                                                      \
        if ((half) == 0 && (((cn) & 3) == 0)) {                               \
            int tap = (cn) >> 2;                                              \
            I  = g_sidx[pixg * 9 + tap];                                      \
            Wq = g_sw[pixg * 9 + tap];                                        \
        }                                                                     \
        const __half* xc = xb + ((cn) & 3) * 64 + s16 + (half) * 8;           \
        c0v = *(const uint4*)(xc + (size_t)I.x * CIN);                        \
        c1v = *(const uint4*)(xc + (size_t)I.y * CIN);                        \
        c2v = *(const uint4*)(xc + (size_t)I.z * CIN);                        \
        c3v = *(const uint4*)(xc + (size_t)I.w * CIN);                        \
    } while (0)

#define GATHER_STORE(stg, half)                                               \
    do {                                                                      \
        const __half2* h0 = (const __half2*)&c0v;                             \
        const __half2* h1 = (const __half2*)&c1v;                             \
        const __half2* h2 = (const __half2*)&c2v;                             \
        const __half2* h3 = (const __half2*)&c3v;                             \
        __half2 outv[4];                                                      \
        _Pragma("unroll")                                                     \
        for (int j = 0; j < 4; j++) {                                         \
            float2 f0 = __half22float2(h0[j]);                                \
            float2 f1 = __half22float2(h1[j]);                                \
            float2 f2 = __half22float2(h2[j]);                                \
            float2 f3 = __half22float2(h3[j]);                                \
            float2 rr;                                                        \
            rr.x = Wq.x * f0.x + Wq.y * f1.x + Wq.z * f2.x + Wq.w * f3.x;     \
            rr.y = Wq.x * f0.y + Wq.y * f1.y + Wq.z * f2.y + Wq.w * f3.y;     \
            outv[j] = __float22half2_rn(rr);                                  \
        }                                                                     \
        *(uint4*)(smem + A_OFF(stg) + (r * ASTRIDE + s16 + (half) * 8) * 2) = \
            *(const uint4*)outv;                                              \
    } while (0)

#define LOAD_B(stg, kc)                                                       \
    do {                                                                      \
        const __half* bs = g_wtB + (size_t)(kc) * 16384                       \
                         + (t >> 1) * 64 + (t & 1) * 32;                      \
        uint32_t bd = sb + B_OFF(stg) + ((t >> 1) * ASTRIDE + (t & 1) * 32) * 2; \
        CP_ASYNC16(bd,      bs);                                              \
        CP_ASYNC16(bd + 16, bs + 8);                                          \
        CP_ASYNC16(bd + 32, bs + 16);                                         \
        CP_ASYNC16(bd + 48, bs + 24);                                         \
        CP_COMMIT();                                                          \
    } while (0)

#define MMA_GROUP(Ab, Bb, ks)                                                 \
    do {                                                                      \
        int col = (ks) + lcol;                                                \
        uint32_t A0[4], A1[4], t0, t1, t2, t3;                                \
        LDMX4(A0[0], A0[1], A0[2], A0[3],                                     \
              (Ab) + ((wm * 32 + lrow) * ASTRIDE + col) * 2);                 \
        LDMX4(A1[0], A1[1], A1[2], A1[3],                                     \
              (Ab) + ((wm * 32 + 16 + lrow) * ASTRIDE + col) * 2);            \
        _Pragma("unroll")                                                     \
        for (int np = 0; np < 4; np++) {                                      \
            LDMX4(t0, t1, t2, t3,                                             \
                  (Bb) + ((wn * 64 + np * 16 + lrow) * ASTRIDE + col) * 2);   \
            MMA16816(acc[0][np * 2], A0, t0, t2);                             \
            MMA16816(acc[1][np * 2], A1, t0, t2);                             \
            MMA16816(acc[0][np * 2 + 1], A0, t1, t3);                         \
            MMA16816(acc[1][np * 2 + 1], A1, t1, t3);                         \
        }                                                                     \
    } while (0)

    // prologue: stage 0
    GATHER_LDG(0, 0);  GATHER_STORE(0, 0);
    GATHER_LDG(0, 1);  GATHER_STORE(0, 1);
    LOAD_B(0, 0);

    for (int c = 0; c < NKC; c++) {
        int st = c & 1;
        bool more = (c + 1 < NKC);
        if (more) GATHER_LDG(c + 1, 0);
        asm volatile("cp.async.wait_group 0;" ::: "memory");
        __syncthreads();
        if (more) LOAD_B(st ^ 1, c + 1);

        uint32_t Ab = sb + A_OFF(st);
        uint32_t Bb = sb + B_OFF(st);
        MMA_GROUP(Ab, Bb, 0);
        MMA_GROUP(Ab, Bb, 16);
        if (more) { GATHER_STORE(st ^ 1, 0); GATHER_LDG(c + 1, 1); }
        MMA_GROUP(Ab, Bb, 32);
        MMA_GROUP(Ab, Bb, 48);
        if (more) GATHER_STORE(st ^ 1, 1);
    }
#undef GATHER_LDG
#undef GATHER_STORE
#undef LOAD_B
#undef MMA_GROUP

    // ---- write P ----
#pragma unroll
    for (int mt = 0; mt < 2; mt++) {
        int row = m0 + wm * 32 + mt * 16 + (lane >> 2);
#pragma unroll
        for (int nt = 0; nt < 8; nt++) {
            int col = wn * 64 + nt * 8 + (lane & 3) * 2;
            *(float2*)&g_P[(size_t)row * COUT + col] =
                make_float2(acc[mt][nt][0], acc[mt][nt][1]);
            *(float2*)&g_P[(size_t)(row + 8) * COUT + col] =
                make_float2(acc[mt][nt][2], acc[mt][nt][3]);
        }
    }

    // ---- GN partial sums (deterministic) ----
    __syncthreads();
    float* sgn = (float*)smem;              // [32 groups][4 wm][2]
#pragma unroll
    for (int nt = 0; nt < 8; nt++) {
        float s = 0.f, ss = 0.f;
#pragma unroll
        for (int mt = 0; mt < 2; mt++)
#pragma unroll
            for (int q = 0; q < 4; q++) {
                float v = acc[mt][nt][q];
                s += v;  ss += v * v;
            }
#pragma unroll
        for (int off = 16; off >= 1; off >>= 1) {
            s  += __shfl_xor_sync(0xffffffffu, s, off);
            ss += __shfl_xor_sync(0xffffffffu, ss, off);
        }
        if (lane == 0) {
            int g = wn * 8 + nt;
            sgn[(g * 4 + wm) * 2 + 0] = s;
            sgn[(g * 4 + wm) * 2 + 1] = ss;
        }
    }
    __syncthreads();
    if (t < GROUPS) {
        float s = 0.f, ss = 0.f;
#pragma unroll
        for (int w = 0; w < 4; w++) {
            s  += sgn[(t * 4 + w) * 2 + 0];
            ss += sgn[(t * 4 + w) * 2 + 1];
        }
        g_gnp[blockIdx.x * GROUPS + t] = make_float2(s, ss);
    }
}

// ---------------------------------------------------------------------------
// K3: combine GN partials -> mean / rstd
// ---------------------------------------------------------------------------
__global__ void k_stats_combine() {
    int t = threadIdx.x;
    int b = t >> 5, g = t & 31;
    float s = 0.f, ss = 0.f;
    for (int blk = 0; blk < 32; blk++) {
        float2 v = g_gnp[(b * 32 + blk) * GROUPS + g];
        s += v.x;  ss += v.y;
    }
    float inv = 1.f / (float)(CPG * HWSZ);
    float mean = s * inv;
    float var  = ss * inv - mean * mean;
    g_stat[t * 2]     = mean;
    g_stat[t * 2 + 1] = rsqrtf(var + 1e-5f);
}

// ---------------------------------------------------------------------------
// K4: normalize + affine + ReLU + NHWC->NCHW into d_out
// ---------------------------------------------------------------------------
__global__ void k_gn_finalize(float* __restrict__ out,
                              const float* __restrict__ gamma,
                              const float* __restrict__ beta) {
    __shared__ float tile[32][33];
    int b = blockIdx.z, hw0 = blockIdx.x * 32, o0 = blockIdx.y * 32;
    int tx = threadIdx.x, ty = threadIdx.y;

    int o = o0 + tx;
    int g = o >> 3;
    float mean = g_stat[(b * GROUPS + g) * 2];
    float rstd = g_stat[(b * GROUPS + g) * 2 + 1];
    float ga = gamma[o], be = beta[o];

#pragma unroll
    for (int i = 0; i < 4; i++) {
        int hw = hw0 + ty + i * 8;
        float v = g_P[(long)(b * HWSZ + hw) * COUT + o];
        v = (v - mean) * rstd * ga + be;
        tile[ty + i * 8][tx] = fmaxf(v, 0.f);
    }
    __syncthreads();
#pragma unroll
    for (int i = 0; i < 4; i++) {
        int oo = o0 + ty + i * 8;
        out[((long)b * COUT + oo) * HWSZ + hw0 + tx] = tile[tx][ty + i * 8];
    }
}

// ---------------------------------------------------------------------------
extern "C" void kernel_launch(void* const* d_in, const int* in_sizes, int n_in,
                              void* d_out, int out_size) {
    const float* x  = (const float*)d_in[0];
    const float* ow = (const float*)d_in[1];
    const float* ob = (const float*)d_in[2];
    const float* dw = (const float*)d_in[3];
    const float* ga = (const float*)d_in[4];
    const float* be = (const float*)d_in[5];
    float* out = (float*)d_out;

    cudaFuncSetAttribute(k_gemm_fused,
                         cudaFuncAttributeMaxDynamicSharedMemorySize, GEMM_SMEM);

    k_prep<<<dim3(128, 10, 4), 256>>>(x, dw, ow);
    k_offconv16<<<128, 256>>>(ob);
    k_gemm_fused<<<128, 512, GEMM_SMEM>>>();
    k_stats_combine<<<1, 128>>>();
    k_gn_finalize<<<dim3(HWSZ / 32, COUT / 32, BATCH), dim3(32, 8)>>>(out, ga, be);
}